// round 10
// baseline (speedup 1.0000x reference)
#include <cuda_runtime.h>
#include <cuda_bf16.h>
#include <cstdint>

// CumulativeNormalizer: x [32, 512, 4000] fp32.
// out[b,f,t] = (x[t] - mean(x[0..t])) / sqrt(var(x[0..t]) + 1e-4)
//
// One 256-thread block per row (R7 structure — high occupancy does the
// cross-block load/compute overlap). Row staged to shared via cp.async
// (padded, conflict-free); thread-local 16-elem totals + warp scan +
// cross-warp combine; epilogue streams results DIRECTLY to global
// (no third smem->global phase, one fewer barrier).
// Identity: out = (x*c - S) * rsqrt(c*Q - S^2 + eps*c^2)  -> 1 MUFU/elem.

#define FRAMES  4000
#define ROWS    (32 * 512)
#define EPS     1e-4f
#define THREADS 256
#define SEG     16
#define ACTIVE  250                            // 250 * 16 = 4000
#define VEC4    (FRAMES / 4)                   // 1000 float4 per row
#define PADDED  (FRAMES + 4 * (FRAMES / 32))   // 4500 floats

__device__ __forceinline__ int padi(int i) { return i + ((i >> 5) << 2); }

__global__ __launch_bounds__(THREADS)
void cumnorm_kernel(const float* __restrict__ x, float* __restrict__ out) {
    __shared__ float sd[PADDED];
    __shared__ float swS[8];
    __shared__ float swQ[8];

    const int tid  = threadIdx.x;
    const int lane = tid & 31;
    const int w    = tid >> 5;
    const int row  = blockIdx.x;

    const float* __restrict__ xr = x   + (size_t)row * FRAMES;
    float*       __restrict__ yr = out + (size_t)row * FRAMES;

    // ---- Stage row -> shared (cp.async.cg, coalesced, padded dst) ----
    const unsigned sbase = (unsigned)__cvta_generic_to_shared(sd);
    #pragma unroll
    for (int k = 0; k < 4; k++) {
        const int i4 = tid + THREADS * k;
        if (i4 < VEC4) {
            const int g = i4 * 4;
            const unsigned dst = sbase + (unsigned)(padi(g) * 4);
            asm volatile("cp.async.cg.shared.global [%0], [%1], 16;\n"
                         :: "r"(dst), "l"(xr + g));
        }
    }
    asm volatile("cp.async.commit_group;\n");
    asm volatile("cp.async.wait_group 0;\n");
    __syncthreads();

    // ---- Per-thread segment totals (S, Q) over 16 contiguous frames ----
    float S = 0.f, Q = 0.f;
    if (tid < ACTIVE) {
        const int p0 = padi(tid * SEG);   // segment contiguous in padded space
        #pragma unroll
        for (int j = 0; j < 4; j++) {
            const float4 v = *reinterpret_cast<const float4*>(&sd[p0 + 4 * j]);
            S += v.x + v.y + v.z + v.w;
            Q = fmaf(v.x, v.x, Q);
            Q = fmaf(v.y, v.y, Q);
            Q = fmaf(v.z, v.z, Q);
            Q = fmaf(v.w, v.w, Q);
        }
    }

    // ---- Warp inclusive scan over segment totals ----
    const unsigned FULL = 0xFFFFFFFFu;
    float is = S, iq = Q;
    #pragma unroll
    for (int off = 1; off < 32; off <<= 1) {
        const float ts = __shfl_up_sync(FULL, is, off);
        const float tq = __shfl_up_sync(FULL, iq, off);
        if (lane >= off) { is += ts; iq += tq; }
    }
    if (lane == 31) { swS[w] = is; swQ[w] = iq; }
    __syncthreads();

    // ---- Cross-warp exclusive offset (broadcast reads) ----
    float offS = 0.f, offQ = 0.f;
    #pragma unroll
    for (int ww = 0; ww < 7; ww++) {
        if (ww < w) { offS += swS[ww]; offQ += swQ[ww]; }
    }
    const float baseS = offS + (is - S);   // exclusive prefix before segment
    const float baseQ = offQ + (iq - Q);

    // ---- Epilogue: accumulate inside segment, store DIRECT to global ----
    if (tid < ACTIVE) {
        const int p0 = padi(tid * SEG);
        float* __restrict__ yseg = yr + tid * SEG;
        float s = baseS, q = baseQ;
        float c = (float)(tid * SEG + 1);
        #pragma unroll
        for (int j = 0; j < 4; j++) {
            const float4 v = *reinterpret_cast<const float4*>(&sd[p0 + 4 * j]);
            float4 o;
            {   s += v.x; q = fmaf(v.x, v.x, q);
                float t = fmaf(c, q, -s * s); t = fmaf(EPS * c, c, t);
                o.x = fmaf(v.x, c, -s) * rsqrtf(t); c += 1.0f; }
            {   s += v.y; q = fmaf(v.y, v.y, q);
                float t = fmaf(c, q, -s * s); t = fmaf(EPS * c, c, t);
                o.y = fmaf(v.y, c, -s) * rsqrtf(t); c += 1.0f; }
            {   s += v.z; q = fmaf(v.z, v.z, q);
                float t = fmaf(c, q, -s * s); t = fmaf(EPS * c, c, t);
                o.z = fmaf(v.z, c, -s) * rsqrtf(t); c += 1.0f; }
            {   s += v.w; q = fmaf(v.w, v.w, q);
                float t = fmaf(c, q, -s * s); t = fmaf(EPS * c, c, t);
                o.w = fmaf(v.w, c, -s) * rsqrtf(t); c += 1.0f; }
            __stcs(reinterpret_cast<float4*>(yseg + 4 * j), o);
        }
    }
}

extern "C" void kernel_launch(void* const* d_in, const int* in_sizes, int n_in,
                              void* d_out, int out_size) {
    const float* x = (const float*)d_in[0];
    float* out = (float*)d_out;
    (void)in_sizes; (void)n_in; (void)out_size;

    cumnorm_kernel<<<ROWS, THREADS>>>(x, out);   // one block per row
}

// round 11
// speedup vs baseline: 1.2066x; 1.2066x over previous
#include <cuda_runtime.h>
#include <cuda_bf16.h>
#include <cstdint>

// CumulativeNormalizer: x [32, 512, 4000] fp32.
// out[b,f,t] = (x[t] - mean(x[0..t])) / sqrt(var(x[0..t]) + 1e-4)
//
// One 128-thread block per row (finer phase granularity: ~12 resident
// blocks/SM instead of 8, so load/compute phases of different blocks
// interleave more densely). Row staged to shared via cp.async (padded,
// conflict-free); thread-local 32-elem totals + warp scan + 4-warp
// combine; epilogue in place in shared; coalesced streaming store.
// Identity: out = (x*c - S) * rsqrt(c*Q - S^2 + eps*c^2)  -> 1 MUFU/elem.

#define FRAMES  4000
#define ROWS    (32 * 512)
#define EPS     1e-4f
#define THREADS 128
#define SEG     32
#define ACTIVE  125                            // 125 * 32 = 4000
#define VEC4    (FRAMES / 4)                   // 1000 float4 per row
#define PADDED  (FRAMES + 4 * (FRAMES / 32))   // 4500 floats (pitch 36/32)
#define NWARPS  (THREADS / 32)

__device__ __forceinline__ int padi(int i) { return i + ((i >> 5) << 2); }

__global__ __launch_bounds__(THREADS)
void cumnorm_kernel(const float* __restrict__ x, float* __restrict__ out) {
    __shared__ float sd[PADDED];
    __shared__ float swS[NWARPS];
    __shared__ float swQ[NWARPS];

    const int tid  = threadIdx.x;
    const int lane = tid & 31;
    const int w    = tid >> 5;
    const int row  = blockIdx.x;

    const float* __restrict__ xr = x   + (size_t)row * FRAMES;
    float*       __restrict__ yr = out + (size_t)row * FRAMES;

    // ---- Stage row -> shared (cp.async.cg, coalesced, padded dst) ----
    const unsigned sbase = (unsigned)__cvta_generic_to_shared(sd);
    #pragma unroll
    for (int k = 0; k < 8; k++) {
        const int i4 = tid + THREADS * k;
        if (i4 < VEC4) {
            const int g = i4 * 4;
            const unsigned dst = sbase + (unsigned)(padi(g) * 4);
            asm volatile("cp.async.cg.shared.global [%0], [%1], 16;\n"
                         :: "r"(dst), "l"(xr + g));
        }
    }
    asm volatile("cp.async.commit_group;\n");
    asm volatile("cp.async.wait_group 0;\n");
    __syncthreads();

    // ---- Per-thread segment totals (S, Q) over 32 contiguous frames ----
    // Segment [32t, 32t+32) never crosses a pad boundary: p0 = 36t, contiguous.
    float S = 0.f, Q = 0.f;
    if (tid < ACTIVE) {
        const int p0 = padi(tid * SEG);
        #pragma unroll
        for (int j = 0; j < 8; j++) {
            const float4 v = *reinterpret_cast<const float4*>(&sd[p0 + 4 * j]);
            S += v.x + v.y + v.z + v.w;
            Q = fmaf(v.x, v.x, Q);
            Q = fmaf(v.y, v.y, Q);
            Q = fmaf(v.z, v.z, Q);
            Q = fmaf(v.w, v.w, Q);
        }
    }

    // ---- Warp inclusive scan over segment totals ----
    const unsigned FULL = 0xFFFFFFFFu;
    float is = S, iq = Q;
    #pragma unroll
    for (int off = 1; off < 32; off <<= 1) {
        const float ts = __shfl_up_sync(FULL, is, off);
        const float tq = __shfl_up_sync(FULL, iq, off);
        if (lane >= off) { is += ts; iq += tq; }
    }
    if (lane == 31) { swS[w] = is; swQ[w] = iq; }
    __syncthreads();

    // ---- Cross-warp exclusive offset (4 warps, broadcast reads) ----
    float offS = 0.f, offQ = 0.f;
    #pragma unroll
    for (int ww = 0; ww < NWARPS - 1; ww++) {
        if (ww < w) { offS += swS[ww]; offQ += swQ[ww]; }
    }
    const float baseS = offS + (is - S);   // exclusive prefix before segment
    const float baseQ = offQ + (iq - Q);

    // ---- Epilogue: running accumulate inside segment, normalize in place ----
    if (tid < ACTIVE) {
        const int p0 = padi(tid * SEG);
        float s = baseS, q = baseQ;
        float c = (float)(tid * SEG + 1);
        #pragma unroll
        for (int j = 0; j < 8; j++) {
            const float4 v = *reinterpret_cast<const float4*>(&sd[p0 + 4 * j]);
            float4 o;
            {   s += v.x; q = fmaf(v.x, v.x, q);
                float t = fmaf(c, q, -s * s); t = fmaf(EPS * c, c, t);
                o.x = fmaf(v.x, c, -s) * rsqrtf(t); c += 1.0f; }
            {   s += v.y; q = fmaf(v.y, v.y, q);
                float t = fmaf(c, q, -s * s); t = fmaf(EPS * c, c, t);
                o.y = fmaf(v.y, c, -s) * rsqrtf(t); c += 1.0f; }
            {   s += v.z; q = fmaf(v.z, v.z, q);
                float t = fmaf(c, q, -s * s); t = fmaf(EPS * c, c, t);
                o.z = fmaf(v.z, c, -s) * rsqrtf(t); c += 1.0f; }
            {   s += v.w; q = fmaf(v.w, v.w, q);
                float t = fmaf(c, q, -s * s); t = fmaf(EPS * c, c, t);
                o.w = fmaf(v.w, c, -s) * rsqrtf(t); c += 1.0f; }
            *reinterpret_cast<float4*>(&sd[p0 + 4 * j]) = o;   // own slots only
        }
    }
    __syncthreads();

    // ---- Unstage: shared -> global, coalesced streaming stores ----
    #pragma unroll
    for (int k = 0; k < 8; k++) {
        const int i4 = tid + THREADS * k;
        if (i4 < VEC4) {
            const int g = i4 * 4;
            const float4 v = *reinterpret_cast<const float4*>(&sd[padi(g)]);
            __stcs(reinterpret_cast<float4*>(yr + g), v);
        }
    }
}

extern "C" void kernel_launch(void* const* d_in, const int* in_sizes, int n_in,
                              void* d_out, int out_size) {
    const float* x = (const float*)d_in[0];
    float* out = (float*)d_out;
    (void)in_sizes; (void)n_in; (void)out_size;

    cumnorm_kernel<<<ROWS, THREADS>>>(x, out);   // one block per row
}